// round 1
// baseline (speedup 1.0000x reference)
#include <cuda_runtime.h>
#include <math.h>

#define B_      32
#define T_      128
#define IN_     512
#define OUT_    512
#define N_      128
#define WD_     64
#define R_      4
#define H_      512
#define IFACE_  471
#define GATES_  2048
#define EPS_    1e-6f
#define LINKS_  129   // padded link row stride (conflict-free both orientations)

struct Smem {
    float M[N_ * WD_];        // 8192
    float link[N_ * LINKS_];  // 16512
    float act[1280];          // x(512) | reads(256) | h(512)
    float c[H_];
    float zbuf[4096];
    float v[472];
    float usage[N_];
    float prec[N_];
    float ww[N_];
    float wr[R_ * N_];
    float Mnorm[N_];
    float skv[N_];
    int   ski[N_];
    float scanbuf[N_];
    float aalloc[N_];
    float cw[N_];
    float crs[R_ * N_];
    float fw[R_ * N_];
    float bw[R_ * N_];
    float erasev[WD_];
    float wvec[WD_];
    float rb[R_];
    float freeg[R_];
    float keynorm[R_];
    float modes[R_ * 3];
    float sc[8];  // 0: wbeta, 1: alloc_g, 2: write_g, 3: wknorm, 4: wsum
};

__device__ __forceinline__ float sigf(float x) { return 1.f / (1.f + expf(-x)); }
__device__ __forceinline__ float softplusf(float x) {
    return fmaxf(x, 0.f) + log1pf(expf(-fabsf(x)));
}
__device__ __forceinline__ float warp_sum(float v) {
    #pragma unroll
    for (int o = 16; o; o >>= 1) v += __shfl_xor_sync(0xffffffffu, v, o);
    return v;
}
__device__ __forceinline__ float warp_max(float v) {
    #pragma unroll
    for (int o = 16; o; o >>= 1) v = fmaxf(v, __shfl_xor_sync(0xffffffffu, v, o));
    return v;
}

__global__ void __launch_bounds__(1024, 1) dnc_kernel(
    const float* __restrict__ x,   const float* __restrict__ Wx,
    const float* __restrict__ Wh,  const float* __restrict__ bl,
    const float* __restrict__ Wif, const float* __restrict__ bif,
    const float* __restrict__ Wo,  const float* __restrict__ bo,
    float* __restrict__ out)
{
    extern __shared__ char smraw[];
    Smem& s = *reinterpret_cast<Smem*>(smraw);
    const int tid  = threadIdx.x;
    const int b    = blockIdx.x;
    const int lane = tid & 31;
    const int wi   = tid >> 5;

    // ---- init state ----
    for (int i = tid; i < N_ * WD_;    i += 1024) s.M[i]    = 0.f;
    for (int i = tid; i < N_ * LINKS_; i += 1024) s.link[i] = 0.f;
    for (int i = tid; i < 1280;        i += 1024) s.act[i]  = 0.f;
    for (int i = tid; i < H_;          i += 1024) s.c[i]    = 0.f;
    if (tid < N_) { s.usage[tid] = 0.f; s.prec[tid] = 0.f; s.ww[tid] = 0.f; s.Mnorm[tid] = 0.f; }
    for (int i = tid; i < R_ * N_; i += 1024) s.wr[i] = 0.f;
    __syncthreads();

    for (int t = 0; t < T_; t++) {
        // ---- load x_t into act[0:512) ----
        if (tid < IN_) s.act[tid] = x[(size_t)b * T_ * IN_ + (size_t)t * IN_ + tid];
        __syncthreads();

        // ---- z = [x,reads] @ Wx + h @ Wh  (2048 cols, float4, 2-way row split) ----
        {
            const int g  = tid & 511;
            const int rh = tid >> 9;
            const int colb = 4 * g;
            float a0 = 0.f, a1 = 0.f, a2 = 0.f, a3 = 0.f;
            if (rh == 0) {
                #pragma unroll 4
                for (int i = 0; i < 640; i++) {
                    float sv = s.act[i];
                    float4 w = *reinterpret_cast<const float4*>(Wx + (size_t)i * GATES_ + colb);
                    a0 = fmaf(sv, w.x, a0); a1 = fmaf(sv, w.y, a1);
                    a2 = fmaf(sv, w.z, a2); a3 = fmaf(sv, w.w, a3);
                }
            } else {
                #pragma unroll 4
                for (int i = 640; i < 768; i++) {
                    float sv = s.act[i];
                    float4 w = *reinterpret_cast<const float4*>(Wx + (size_t)i * GATES_ + colb);
                    a0 = fmaf(sv, w.x, a0); a1 = fmaf(sv, w.y, a1);
                    a2 = fmaf(sv, w.z, a2); a3 = fmaf(sv, w.w, a3);
                }
                #pragma unroll 4
                for (int j = 0; j < 512; j++) {
                    float sv = s.act[768 + j];
                    float4 w = *reinterpret_cast<const float4*>(Wh + (size_t)j * GATES_ + colb);
                    a0 = fmaf(sv, w.x, a0); a1 = fmaf(sv, w.y, a1);
                    a2 = fmaf(sv, w.z, a2); a3 = fmaf(sv, w.w, a3);
                }
                s.zbuf[colb] = a0; s.zbuf[colb + 1] = a1;
                s.zbuf[colb + 2] = a2; s.zbuf[colb + 3] = a3;
            }
            __syncthreads();
            if (rh == 0) {
                s.zbuf[colb]     += a0; s.zbuf[colb + 1] += a1;
                s.zbuf[colb + 2] += a2; s.zbuf[colb + 3] += a3;
            }
            __syncthreads();
        }

        // ---- LSTM pointwise: c,h update ----
        if (tid < H_) {
            int j = tid;
            float zi = s.zbuf[j]        + bl[j];
            float zf = s.zbuf[512 + j]  + bl[512 + j];
            float zg = s.zbuf[1024 + j] + bl[1024 + j];
            float zo = s.zbuf[1536 + j] + bl[1536 + j];
            float cn = sigf(zf) * s.c[j] + sigf(zi) * tanhf(zg);
            float hn = sigf(zo) * tanhf(cn);
            s.c[j] = cn;
            s.act[768 + j] = hn;
        }
        __syncthreads();

        // ---- iface: v = h_n @ W_iface + b_iface (471 cols, 2-way row split) ----
        {
            float acc = 0.f;
            int col = tid % IFACE_;
            int half = tid / IFACE_;
            if (tid < 2 * IFACE_) {
                int r0 = half * 256;
                for (int i = r0; i < r0 + 256; i++)
                    acc = fmaf(s.act[768 + i], Wif[(size_t)i * IFACE_ + col], acc);
                if (half == 1) s.zbuf[col] = acc;
            }
            __syncthreads();
            if (tid < IFACE_) s.v[tid] = acc + s.zbuf[tid] + bif[tid];
            __syncthreads();
        }

        // ---- iface transforms + key norms ----
        if (tid < R_) { s.rb[tid] = 1.f + softplusf(s.v[256 + tid]); s.freeg[tid] = sigf(s.v[453 + tid]); }
        if (tid == 8)  s.sc[0] = 1.f + softplusf(s.v[324]);
        if (tid == 9)  s.sc[1] = sigf(s.v[457]);
        if (tid == 10) s.sc[2] = sigf(s.v[458]);
        if (tid >= 64 && tid < 128) {
            int w = tid - 64;
            s.erasev[w] = sigf(s.v[325 + w]);
            s.wvec[w]   = s.v[389 + w];
        }
        if (tid >= 128 && tid < 132) {
            int r = tid - 128;
            float m0 = s.v[459 + 3 * r], m1 = s.v[460 + 3 * r], m2 = s.v[461 + 3 * r];
            float mx = fmaxf(m0, fmaxf(m1, m2));
            float e0 = expf(m0 - mx), e1 = expf(m1 - mx), e2 = expf(m2 - mx);
            float ssum = e0 + e1 + e2;
            s.modes[3 * r] = e0 / ssum; s.modes[3 * r + 1] = e1 / ssum; s.modes[3 * r + 2] = e2 / ssum;
        }
        if (wi >= 4 && wi < 8) {  // read-key norms
            int r = wi - 4;
            float kv = s.v[r * 64 + lane], kv2 = s.v[r * 64 + lane + 32];
            float ssum = warp_sum(kv * kv + kv2 * kv2);
            if (lane == 0) s.keynorm[r] = sqrtf(ssum);
        }
        if (wi == 8) {            // write-key norm
            float kv = s.v[260 + lane], kv2 = s.v[260 + lane + 32];
            float ssum = warp_sum(kv * kv + kv2 * kv2);
            if (lane == 0) s.sc[3] = sqrtf(ssum);
        }
        __syncthreads();

        // ---- usage update (old wr, old ww) ----
        if (tid < N_) {
            float ret = 1.f;
            #pragma unroll
            for (int r = 0; r < R_; r++) ret *= (1.f - s.freeg[r] * s.wr[r * N_ + tid]);
            float u = s.usage[tid], w0 = s.ww[tid];
            float un = (u + w0 - u * w0) * ret;
            s.usage[tid] = un;
            s.skv[tid] = un; s.ski[tid] = tid;
        }
        __syncthreads();

        // ---- stable bitonic sort of (usage, index) ascending ----
        for (int k = 2; k <= N_; k <<= 1) {
            for (int j = k >> 1; j > 0; j >>= 1) {
                if (tid < N_) {
                    int ixj = tid ^ j;
                    if (ixj > tid) {
                        float va = s.skv[tid], vb = s.skv[ixj];
                        int ia = s.ski[tid], ib = s.ski[ixj];
                        bool up = ((tid & k) == 0);
                        bool agtb = (va > vb) || (va == vb && ia > ib);
                        bool dosw = up ? agtb : !agtb;
                        if (dosw) {
                            s.skv[tid] = vb; s.skv[ixj] = va;
                            s.ski[tid] = ib; s.ski[ixj] = ia;
                        }
                    }
                }
                __syncthreads();
            }
        }
        // ---- cumprod (Hillis-Steele) + allocation scatter ----
        if (tid < N_) s.scanbuf[tid] = s.skv[tid];
        __syncthreads();
        for (int off = 1; off < N_; off <<= 1) {
            float pv = 1.f;
            if (tid < N_ && tid >= off) pv = s.scanbuf[tid - off];
            __syncthreads();
            if (tid < N_ && tid >= off) s.scanbuf[tid] *= pv;
            __syncthreads();
        }
        if (tid < N_) {
            float excl = (tid > 0) ? s.scanbuf[tid - 1] : 1.f;
            s.aalloc[s.ski[tid]] = (1.f - s.skv[tid]) * excl;
        }
        __syncthreads();

        // ---- write content weights cw (old M, old Mnorm) ----
        {
            float wb = s.sc[0], wkn = s.sc[3];
            #pragma unroll
            for (int o = 0; o < 4; o++) {
                int n = wi + o * 32;
                float d = s.M[n * 64 + lane] * s.v[260 + lane]
                        + s.M[n * 64 + lane + 32] * s.v[260 + lane + 32];
                d = warp_sum(d);
                if (lane == 0) s.cw[n] = wb * d / ((s.Mnorm[n] + EPS_) * (wkn + EPS_));
            }
            __syncthreads();
            if (wi == 0) {
                float a0 = s.cw[lane], a1 = s.cw[lane + 32], a2 = s.cw[lane + 64], a3 = s.cw[lane + 96];
                float mx = warp_max(fmaxf(fmaxf(a0, a1), fmaxf(a2, a3)));
                float e0 = expf(a0 - mx), e1 = expf(a1 - mx), e2 = expf(a2 - mx), e3 = expf(a3 - mx);
                float su = warp_sum(e0 + e1 + e2 + e3);
                float inv = 1.f / su;
                s.cw[lane] = e0 * inv; s.cw[lane + 32] = e1 * inv;
                s.cw[lane + 64] = e2 * inv; s.cw[lane + 96] = e3 * inv;
            }
            __syncthreads();
        }

        // ---- ww_n ----
        if (tid < N_) {
            float ag = s.sc[1], wg = s.sc[2];
            s.ww[tid] = wg * (ag * s.aalloc[tid] + (1.f - ag) * s.cw[tid]);
        }
        __syncthreads();
        if (wi == 0) {
            float ssum = warp_sum(s.ww[lane] + s.ww[lane + 32] + s.ww[lane + 64] + s.ww[lane + 96]);
            if (lane == 0) s.sc[4] = ssum;
        }
        // ---- M update ----
        for (int idx = tid; idx < N_ * WD_; idx += 1024) {
            int n = idx >> 6, w = idx & 63;
            float wwn = s.ww[n];
            s.M[idx] = s.M[idx] * (1.f - wwn * s.erasev[w]) + wwn * s.wvec[w];
        }
        // ---- link update (old prec) ----
        for (int idx = tid; idx < N_ * N_; idx += 1024) {
            int i = idx >> 7, j = idx & 127;
            float wwi = s.ww[i], wwj = s.ww[j];
            float nv = (1.f - wwi - wwj) * s.link[i * LINKS_ + j] + wwi * s.prec[j];
            if (i == j) nv = 0.f;
            s.link[i * LINKS_ + j] = nv;
        }
        __syncthreads();
        // ---- prec update ----
        if (tid < N_) s.prec[tid] = (1.f - s.sc[4]) * s.prec[tid] + s.ww[tid];
        // ---- Mnorm recompute (new M; also used next step for write content) ----
        #pragma unroll
        for (int o = 0; o < 4; o++) {
            int n = wi + o * 32;
            float a = s.M[n * 64 + lane], b2 = s.M[n * 64 + lane + 32];
            float sq = warp_sum(a * a + b2 * b2);
            if (lane == 0) s.Mnorm[n] = sqrtf(sq);
        }
        __syncthreads();

        // ---- fw / bw (new link, OLD wr). stride-129 keeps both conflict-free ----
        if (tid < 512) {
            int r = tid >> 7, i = tid & 127;
            float acc = 0.f;
            #pragma unroll 4
            for (int j = 0; j < N_; j++) acc = fmaf(s.link[i * LINKS_ + j], s.wr[r * N_ + j], acc);
            s.fw[tid] = acc;
        } else {
            int q = tid - 512; int r = q >> 7, i = q & 127;
            float acc = 0.f;
            #pragma unroll 4
            for (int j = 0; j < N_; j++) acc = fmaf(s.link[j * LINKS_ + i], s.wr[r * N_ + j], acc);
            s.bw[q] = acc;
        }
        // ---- read content sims (new M) ----
        #pragma unroll
        for (int o = 0; o < 16; o++) {
            int id = wi * 16 + o;
            int r = id >> 7, n = id & 127;
            float d = s.M[n * 64 + lane] * s.v[r * 64 + lane]
                    + s.M[n * 64 + lane + 32] * s.v[r * 64 + lane + 32];
            d = warp_sum(d);
            if (lane == 0) s.crs[id] = s.rb[r] * d / ((s.Mnorm[n] + EPS_) * (s.keynorm[r] + EPS_));
        }
        __syncthreads();
        // ---- per-r softmax of read sims (4 warps) ----
        if (wi < 4) {
            int r = wi;
            float a0 = s.crs[r * N_ + lane],      a1 = s.crs[r * N_ + lane + 32];
            float a2 = s.crs[r * N_ + lane + 64], a3 = s.crs[r * N_ + lane + 96];
            float mx = warp_max(fmaxf(fmaxf(a0, a1), fmaxf(a2, a3)));
            float e0 = expf(a0 - mx), e1 = expf(a1 - mx), e2 = expf(a2 - mx), e3 = expf(a3 - mx);
            float su = warp_sum(e0 + e1 + e2 + e3);
            float inv = 1.f / su;
            s.crs[r * N_ + lane] = e0 * inv;      s.crs[r * N_ + lane + 32] = e1 * inv;
            s.crs[r * N_ + lane + 64] = e2 * inv; s.crs[r * N_ + lane + 96] = e3 * inv;
        }
        __syncthreads();
        // ---- wr_n ----
        if (tid < 512) {
            int r = tid >> 7;
            s.wr[tid] = s.modes[3 * r] * s.bw[tid] + s.modes[3 * r + 1] * s.crs[tid]
                      + s.modes[3 * r + 2] * s.fw[tid];
        }
        __syncthreads();
        // ---- reads_n = wr_n @ M  (256 outputs x 4 n-chunks) ----
        {
            int outi = tid & 255;
            int chunk = tid >> 8;
            int r = outi >> 6, w = outi & 63;
            float acc = 0.f;
            int n0 = chunk * 32;
            #pragma unroll 4
            for (int n = n0; n < n0 + 32; n++)
                acc = fmaf(s.wr[r * N_ + n], s.M[n * 64 + w], acc);
            s.zbuf[chunk * 256 + outi] = acc;
        }
        __syncthreads();
        if (tid < 256)
            s.act[512 + tid] = s.zbuf[tid] + s.zbuf[256 + tid] + s.zbuf[512 + tid] + s.zbuf[768 + tid];
        __syncthreads();

        // ---- out = [reads_n, h_n] @ W_out + b_out  (float4, 8-way row split) ----
        {
            int g2 = tid & 127, part = tid >> 7;
            int colb = 4 * g2;
            float a0 = 0.f, a1 = 0.f, a2 = 0.f, a3 = 0.f;
            int i0 = part * 96;
            #pragma unroll 4
            for (int i = i0; i < i0 + 96; i++) {
                float sv = s.act[512 + i];
                float4 w = *reinterpret_cast<const float4*>(Wo + (size_t)i * OUT_ + colb);
                a0 = fmaf(sv, w.x, a0); a1 = fmaf(sv, w.y, a1);
                a2 = fmaf(sv, w.z, a2); a3 = fmaf(sv, w.w, a3);
            }
            s.zbuf[part * 512 + colb]     = a0; s.zbuf[part * 512 + colb + 1] = a1;
            s.zbuf[part * 512 + colb + 2] = a2; s.zbuf[part * 512 + colb + 3] = a3;
        }
        __syncthreads();
        if (tid < OUT_) {
            float acc = bo[tid];
            #pragma unroll
            for (int p = 0; p < 8; p++) acc += s.zbuf[p * 512 + tid];
            out[(size_t)b * T_ * OUT_ + (size_t)t * OUT_ + tid] = acc;
        }
        __syncthreads();
    }
}

extern "C" void kernel_launch(void* const* d_in, const int* in_sizes, int n_in,
                              void* d_out, int out_size) {
    (void)in_sizes; (void)n_in; (void)out_size;
    const float* x   = (const float*)d_in[0];
    const float* Wx  = (const float*)d_in[1];
    const float* Wh  = (const float*)d_in[2];
    const float* bl  = (const float*)d_in[3];
    const float* Wif = (const float*)d_in[4];
    const float* bif = (const float*)d_in[5];
    const float* Wo  = (const float*)d_in[6];
    const float* bo  = (const float*)d_in[7];
    float* out = (float*)d_out;

    cudaFuncSetAttribute(dnc_kernel, cudaFuncAttributeMaxDynamicSharedMemorySize,
                         (int)sizeof(Smem));
    dnc_kernel<<<B_, 1024, sizeof(Smem)>>>(x, Wx, Wh, bl, Wif, bif, Wo, bo, out);
}